// round 2
// baseline (speedup 1.0000x reference)
#include <cuda_runtime.h>
#include <cuda_bf16.h>

// Problem constants (from reference)
#define NUM_IDS   100000
#define FEAT_DIM  512
#define BATCH     512
#define KNEG      100
#define MARGIN    0.03f

#define WARPS_PER_BLOCK 8
#define THREADS_MAIN    (WARPS_PER_BLOCK * 32)
#define TOTAL_TASKS     (BATCH * KNEG)                   // 51200 warp-tasks
#define MAIN_BLOCKS     (TOTAL_TASKS / WARPS_PER_BLOCK)  // 6400

// Scratch (no cudaMalloc allowed)
__device__ int   g_label_map[NUM_IDS];
__device__ float g_partials[MAIN_BLOCKS];

__device__ __forceinline__ int clampi(int v, int lo, int hi) {
    return v < lo ? lo : (v > hi ? hi : v);
}

// ---------------------------------------------------------------------------
// Kernel 1: reset label map to -1
// ---------------------------------------------------------------------------
__global__ void init_map_kernel() {
    int i = blockIdx.x * blockDim.x + threadIdx.x;
    int stride = gridDim.x * blockDim.x;
    for (; i < NUM_IDS; i += stride) g_label_map[i] = -1;
}

// ---------------------------------------------------------------------------
// Kernel 2: scatter "last write wins" -> max batch index per label
// (matches sequential scatter semantics of jnp .at[label].set for dup labels)
// ---------------------------------------------------------------------------
__global__ void set_map_kernel(const int* __restrict__ label) {
    int b = blockIdx.x * blockDim.x + threadIdx.x;
    if (b < BATCH) {
        int l = clampi(label[b], 0, NUM_IDS - 1);
        atomicMax(&g_label_map[l], b);
    }
}

// ---------------------------------------------------------------------------
// Kernel 3: main — one warp per (b, k) pair.
// gi = protos[neg] where protos rows at labels are overridden by teachor_ftr.
// loss_{b,k} = relu( gi.ftr[b] - gi.teachor_ftr[b] - MARGIN )
// Block-sums written to g_partials (deterministic per block).
// ---------------------------------------------------------------------------
__global__ void __launch_bounds__(THREADS_MAIN)
couple_loss_main(const float* __restrict__ ftr,
                 const float* __restrict__ tftr,
                 const int* __restrict__ label,
                 const float* __restrict__ protos,
                 const int* __restrict__ idH) {
    const int warp_in_blk = threadIdx.x >> 5;
    const int lane        = threadIdx.x & 31;
    const int task        = blockIdx.x * WARPS_PER_BLOCK + warp_in_blk;

    const int b = task / KNEG;
    const int k = task - b * KNEG;

    const int lab = clampi(label[b], 0, NUM_IDS - 1);
    const int neg = clampi(idH[lab * KNEG + k], 0, NUM_IDS - 1);

    // Redirect gather if this prototype row was overwritten by the scatter
    const int bsrc = g_label_map[neg];
    const float* __restrict__ row =
        (bsrc >= 0) ? (tftr + (size_t)bsrc * FEAT_DIM)
                    : (protos + (size_t)neg * FEAT_DIM);

    const float4* __restrict__ g = (const float4*)row;
    const float4* __restrict__ f = (const float4*)(ftr  + (size_t)b * FEAT_DIM);
    const float4* __restrict__ t = (const float4*)(tftr + (size_t)b * FEAT_DIM);

    float s = 0.f;   // gi . ftr      (smrs)
    float m = 0.f;   // gi . teachor  (tmrs)
#pragma unroll
    for (int j = 0; j < FEAT_DIM / 4 / 32; ++j) {   // 4 iterations
        const int idx = lane + 32 * j;
        float4 gv = g[idx];
        float4 fv = f[idx];
        float4 tv = t[idx];
        s = fmaf(gv.x, fv.x, s); s = fmaf(gv.y, fv.y, s);
        s = fmaf(gv.z, fv.z, s); s = fmaf(gv.w, fv.w, s);
        m = fmaf(gv.x, tv.x, m); m = fmaf(gv.y, tv.y, m);
        m = fmaf(gv.z, tv.z, m); m = fmaf(gv.w, tv.w, m);
    }

    // Warp reduce both dots
#pragma unroll
    for (int off = 16; off > 0; off >>= 1) {
        s += __shfl_xor_sync(0xffffffffu, s, off);
        m += __shfl_xor_sync(0xffffffffu, m, off);
    }

    __shared__ float warp_loss[WARPS_PER_BLOCK];
    if (lane == 0) warp_loss[warp_in_blk] = fmaxf(s - m - MARGIN, 0.f);
    __syncthreads();

    if (threadIdx.x == 0) {
        float acc = 0.f;
#pragma unroll
        for (int w = 0; w < WARPS_PER_BLOCK; ++w) acc += warp_loss[w];
        g_partials[blockIdx.x] = acc;
    }
}

// ---------------------------------------------------------------------------
// Kernel 4: deterministic final reduction over 6400 block partials
// ---------------------------------------------------------------------------
__global__ void __launch_bounds__(256)
final_reduce(float* __restrict__ out) {
    __shared__ float sh[256];
    float acc = 0.f;
    for (int i = threadIdx.x; i < MAIN_BLOCKS; i += 256) acc += g_partials[i];
    sh[threadIdx.x] = acc;
    __syncthreads();
#pragma unroll
    for (int off = 128; off > 0; off >>= 1) {
        if (threadIdx.x < off) sh[threadIdx.x] += sh[threadIdx.x + off];
        __syncthreads();
    }
    if (threadIdx.x == 0)
        out[0] = sh[0] * (1.0f / (float)(BATCH * KNEG));
}

// ---------------------------------------------------------------------------
extern "C" void kernel_launch(void* const* d_in, const int* in_sizes, int n_in,
                              void* d_out, int out_size) {
    const float* ftr    = (const float*)d_in[0];
    const float* tftr   = (const float*)d_in[1];
    const int*   label  = (const int*)d_in[2];
    const float* protos = (const float*)d_in[3];
    const int*   idH    = (const int*)d_in[4];
    float* out = (float*)d_out;

    init_map_kernel<<<256, 256>>>();
    set_map_kernel<<<(BATCH + 255) / 256, 256>>>(label);
    couple_loss_main<<<MAIN_BLOCKS, THREADS_MAIN>>>(ftr, tftr, label, protos, idH);
    final_reduce<<<1, 256>>>(out);
}